// round 9
// baseline (speedup 1.0000x reference)
#include <cuda_runtime.h>
#include <cstdint>

// ---- problem constants ----
#define BATCH   1024
#define NNODES  100
#define KD      640      // key dim (5*128)
#define KD4     160      // key dim in float4
#define POOL    128
#define TOPK    4
#define PD      2304     // prompt dim
#define PD4     576

// ---- output layout (flat float32, reference return order) ----
#define OUT_RS  (BATCH*TOPK*PD)          // 9437184
#define OUT_SIM (OUT_RS + 1)             // 9437185
#define OUT_US  (OUT_SIM + BATCH*POOL)   // 9568257

// ---- device scratch ----
__device__ float g_xnorm[BATCH * KD];
__device__ float g_keynorm[POOL * KD];
__device__ int   g_idx[BATCH * TOPK];
__device__ float g_partial[128];

// ---- f32x2 packed-FMA helpers (sm_103a) ----
__device__ __forceinline__ void fma2(unsigned long long& acc,
                                     unsigned long long a,
                                     unsigned long long b) {
    asm("fma.rn.f32x2 %0, %1, %2, %0;" : "+l"(acc) : "l"(a), "l"(b));
}
__device__ __forceinline__ float unpack_sum(unsigned long long v) {
    float lo, hi;
    asm("mov.b64 {%0, %1}, %2;" : "=f"(lo), "=f"(hi) : "l"(v));
    return lo + hi;
}

// ============================================================
// kkey: normalize pool keys. 128 blocks x 160 threads.
// ============================================================
__global__ __launch_bounds__(160) void kkey(const float4* __restrict__ pk) {
    const int p = blockIdx.x;
    const int c = threadIdx.x;
    float4 v = pk[(size_t)p * KD4 + c];
    float ss = v.x*v.x + v.y*v.y + v.z*v.z + v.w*v.w;
    #pragma unroll
    for (int o = 16; o; o >>= 1) ss += __shfl_xor_sync(0xffffffffu, ss, o);

    __shared__ float wss[5];
    if ((c & 31) == 0) wss[c >> 5] = ss;
    __syncthreads();
    float tot = wss[0] + wss[1] + wss[2] + wss[3] + wss[4];
    tot = fmaxf(tot, 1e-12f);
    float rs = rsqrtf(tot);
    rs = rs * (1.5f - 0.5f * tot * rs * rs);   // NR refine

    float4* o4 = reinterpret_cast<float4*>(g_keynorm);
    o4[(size_t)p * KD4 + c] = make_float4(v.x*rs, v.y*rs, v.z*rs, v.w*rs);
}

// ============================================================
// kx: per-row mean + L2 normalize (one row per block, (160,2)).
// Normalizing the SUM == normalizing the mean (scale invariance).
// ============================================================
__global__ __launch_bounds__(320, 4) void kx(const float4* __restrict__ x,
                                             int rowBase) {
    const int c   = threadIdx.x;                        // 0..159
    const int tid = threadIdx.y * 160 + threadIdx.x;
    const int lane = tid & 31, warp = tid >> 5;

    __shared__ float4 part[160];
    __shared__ float  wss[10];

    const int row = rowBase + blockIdx.x;
    const float4* xp = x + (size_t)row * (NNODES * KD4)
                         + (size_t)threadIdx.y * 50 * KD4 + c;
    float4 a = make_float4(0.f, 0.f, 0.f, 0.f);
    #pragma unroll 10
    for (int n = 0; n < 50; n++) {
        float4 v = xp[(size_t)n * KD4];
        a.x += v.x; a.y += v.y; a.z += v.z; a.w += v.w;
    }
    if (threadIdx.y == 1) part[c] = a;
    __syncthreads();
    float ss = 0.f;
    if (threadIdx.y == 0) {
        float4 b = part[c];
        a.x += b.x; a.y += b.y; a.z += b.z; a.w += b.w;
        ss = a.x*a.x + a.y*a.y + a.z*a.z + a.w*a.w;
    }
    #pragma unroll
    for (int o = 16; o; o >>= 1) ss += __shfl_xor_sync(0xffffffffu, ss, o);
    if (lane == 0) wss[warp] = ss;
    __syncthreads();
    if (threadIdx.y == 0) {
        float tot = wss[0] + wss[1] + wss[2] + wss[3] + wss[4];
        tot = fmaxf(tot, 1e-12f);
        float rs = rsqrtf(tot);
        rs = rs * (1.5f - 0.5f * tot * rs * rs);
        float4* o4 = reinterpret_cast<float4*>(g_xnorm);
        o4[(size_t)row * KD4 + c] = make_float4(a.x*rs, a.y*rs, a.z*rs, a.w*rs);
    }
}

// ============================================================
// kB: sim GEMM (8 rows x 128 pools per block) + top-4 + partials.
// 64 blocks x 512 threads per chunk. Keys via coalesced LDG (L2),
// x staged once in smem, f32x2 packed FMA.
// ============================================================
__global__ __launch_bounds__(512) void kB_sim_topk(float* __restrict__ out,
                                                   int rowBase) {
    __shared__ float xs[8][644];
    __shared__ float sims[8][132];
    __shared__ float wsum[8];

    const int t = threadIdx.x;
    const int w = t >> 5, lane = t & 31;
    const int pg = t >> 4;             // 0..31 -> pools pg*4..+3
    const int ds = t & 15;             // dim slot
    const int rb = rowBase + blockIdx.x * 8;

    {
        const float4* xg = reinterpret_cast<const float4*>(g_xnorm);
        #pragma unroll
        for (int i = 0; i < 3; i++) {
            int l = t + 512 * i;                // covers 1280
            if (l < 1280) {
                int r = l / 160, col = l - r * 160;
                *reinterpret_cast<float4*>(&xs[r][col * 4]) =
                    xg[(size_t)(rb + r) * KD4 + col];
            }
        }
    }
    __syncthreads();

    const ulonglong2* kg = reinterpret_cast<const ulonglong2*>(g_keynorm);

    unsigned long long acc[4][8];      // [pool u][row r]
    #pragma unroll
    for (int u = 0; u < 4; u++)
        #pragma unroll
        for (int r = 0; r < 8; r++) acc[u][r] = 0ull;

    #pragma unroll
    for (int c = 0; c < 10; c++) {
        ulonglong2 kv[4];
        #pragma unroll
        for (int u = 0; u < 4; u++)
            kv[u] = kg[(size_t)(pg * 4 + u) * KD4 + c * 16 + ds];
        #pragma unroll
        for (int r = 0; r < 8; r++) {
            ulonglong2 xv = *reinterpret_cast<const ulonglong2*>(
                &xs[r][c * 64 + ds * 4]);
            #pragma unroll
            for (int u = 0; u < 4; u++) {
                fma2(acc[u][r], xv.x, kv[u].x);
                fma2(acc[u][r], xv.y, kv[u].y);
            }
        }
    }

    #pragma unroll
    for (int u = 0; u < 4; u++) {
        #pragma unroll
        for (int r = 0; r < 8; r++) {
            float v = unpack_sum(acc[u][r]);
            #pragma unroll
            for (int o = 8; o; o >>= 1) v += __shfl_xor_sync(0xffffffffu, v, o);
            if (ds == 0) sims[r][pg * 4 + u] = v;
        }
    }
    __syncthreads();

    // similarity output (coalesced)
    for (int l = t; l < 8 * POOL; l += 512) {
        int rr = l >> 7, pp = l & 127;
        out[OUT_SIM + (size_t)(rb + rr) * POOL + pp] = sims[rr][pp];
    }

    // top-4: warps 0..7 -> rows 0..7 (monotone-bits composite key,
    // smallest index on ties -> matches jax.lax.top_k)
    if (w < 8) {
        float vals[4];
        #pragma unroll
        for (int s = 0; s < 4; s++) vals[s] = sims[w][lane + 32*s];
        float vsum = 0.f;
        #pragma unroll
        for (int k = 0; k < TOPK; k++) {
            unsigned long long best = 0ull;
            #pragma unroll
            for (int s = 0; s < 4; s++) {
                unsigned u = __float_as_uint(vals[s]);
                u = (u & 0x80000000u) ? ~u : (u | 0x80000000u);
                unsigned long long comp =
                    ((unsigned long long)u << 32) | (127u - (lane + 32u*s));
                if (comp > best) best = comp;
            }
            #pragma unroll
            for (int o = 16; o; o >>= 1) {
                unsigned long long other = __shfl_xor_sync(0xffffffffu, best, o);
                if (other > best) best = other;
            }
            unsigned pool = 127u - (unsigned)(best & 0xffffffffu);
            unsigned ub = (unsigned)(best >> 32);
            unsigned orig = (ub & 0x80000000u) ? (ub ^ 0x80000000u) : ~ub;
            vsum += __uint_as_float(orig);
            if (lane == (int)(pool & 31u)) vals[pool >> 5] = -1e30f;
            if (lane == 0) g_idx[(rb + w) * TOPK + k] = (int)pool;
        }
        if (lane == 0) wsum[w] = vsum;
    }
    __syncthreads();

    if (t == 0) {
        float s = 0.f;
        #pragma unroll
        for (int i = 0; i < 8; i++) s += wsum[i];   // fixed order -> deterministic
        g_partial[rowBase / 8 + blockIdx.x] = s;
    }
}

// ============================================================
// kC: gather selected prompts (9 independent float4/thread).
// ============================================================
__global__ __launch_bounds__(256) void kC_gather(const float4* __restrict__ prompt,
                                                 float* __restrict__ out,
                                                 int rowBase) {
    const int b = rowBase + blockIdx.x;
    const int t = threadIdx.x;
    int idxs[TOPK];
    #pragma unroll
    for (int k = 0; k < TOPK; k++) idxs[k] = g_idx[b * TOPK + k];

    float4 vals[9];
    #pragma unroll
    for (int j = 0; j < 9; j++) {
        int pos = t + 256 * j;          // 0..2303 over [K=4][PD4=576]
        int k   = pos / PD4;
        int off = pos - k * PD4;
        vals[j] = prompt[(size_t)idxs[k] * PD4 + off];
    }
    float4* dst = reinterpret_cast<float4*>(out) + (size_t)b * (TOPK * PD4);
    #pragma unroll
    for (int j = 0; j < 9; j++) dst[t + 256 * j] = vals[j];
}

// ============================================================
// kfinal: reduce_sim (fixed-order tree) + usage histogram.
// ============================================================
__global__ __launch_bounds__(512) void kfinal(float* __restrict__ out) {
    __shared__ float red[128];
    __shared__ int   histo[128];
    const int t = threadIdx.x;
    if (t < 128) { red[t] = g_partial[t]; histo[t] = 0; }
    __syncthreads();
    #pragma unroll
    for (int o = 64; o; o >>= 1) {
        if (t < o) red[t] += red[t + o];
        __syncthreads();
    }
    if (t == 0) out[OUT_RS] = red[0] * (1.0f / (float)BATCH);
    #pragma unroll
    for (int j = 0; j < 8; j++)
        atomicAdd(&histo[g_idx[t * 8 + j]], 1);
    __syncthreads();
    if (t < 128) out[OUT_US + t] = (float)histo[t];
}

// ============================================================
// Forked-stream pipeline: stream 0 (capture origin) streams x in two
// 512-row chunks; side stream runs key-norm, then sim/top-k + gather of
// chunk j overlapped with chunk j+1's streaming. Join before final.
// Stream/events are host-side resources (no device memory); created
// fresh per call (kernel_launch runs ~twice: correctness + capture).
// ============================================================
extern "C" void kernel_launch(void* const* d_in, const int* in_sizes, int n_in,
                              void* d_out, int out_size) {
    const float* x      = (const float*)d_in[0];  // [1024, 100, 640]
    const float* prompt = (const float*)d_in[1];  // [128, 1, 2304]
    const float* pkey   = (const float*)d_in[2];  // [128, 640]
    float* out = (float*)d_out;

    const float4* x4 = reinterpret_cast<const float4*>(x);
    const float4* p4 = reinterpret_cast<const float4*>(prompt);
    const float4* k4 = reinterpret_cast<const float4*>(pkey);

    cudaStream_t s1;
    cudaStreamCreateWithFlags(&s1, cudaStreamNonBlocking);
    cudaEvent_t e0, e1, eJ;
    cudaEventCreateWithFlags(&e0, cudaEventDisableTiming);
    cudaEventCreateWithFlags(&e1, cudaEventDisableTiming);
    cudaEventCreateWithFlags(&eJ, cudaEventDisableTiming);

    // side stream: key normalize (independent of x)
    kkey<<<128, 160, 0, s1>>>(k4);

    // main stream: x chunk A
    kx<<<512, dim3(160, 2)>>>(x4, 0);
    cudaEventRecord(e0, 0);
    // main stream: x chunk B (overlaps side-stream consumers of chunk A)
    kx<<<512, dim3(160, 2)>>>(x4, 512);
    cudaEventRecord(e1, 0);

    // side stream: consume chunk A
    cudaStreamWaitEvent(s1, e0, 0);
    kB_sim_topk<<<64, 512, 0, s1>>>(out, 0);
    kC_gather<<<512, 256, 0, s1>>>(p4, out, 0);
    // side stream: consume chunk B
    cudaStreamWaitEvent(s1, e1, 0);
    kB_sim_topk<<<64, 512, 0, s1>>>(out, 512);
    kC_gather<<<512, 256, 0, s1>>>(p4, out, 512);
    cudaEventRecord(eJ, s1);

    // join + final
    cudaStreamWaitEvent(0, eJ, 0);
    kfinal<<<1, 512>>>(out);
}

// round 10
// speedup vs baseline: 1.0291x; 1.0291x over previous
#include <cuda_runtime.h>
#include <cstdint>

// ---- problem constants ----
#define BATCH   1024
#define NNODES  100
#define KD      640      // key dim (5*128)
#define KD4     160      // key dim in float4
#define POOL    128
#define TOPK    4
#define PD      2304     // prompt dim
#define PD4     576

// ---- output layout (flat float32, reference return order) ----
#define OUT_RS  (BATCH*TOPK*PD)          // 9437184
#define OUT_SIM (OUT_RS + 1)             // 9437185
#define OUT_US  (OUT_SIM + BATCH*POOL)   // 9568257

// ---- merged-kernel roles ----
#define M_GATHER0 128                    // sims: 0..127, gathers: 128..1151
#define M_FIN     1152
#define M_BLOCKS  1153

// ---- device scratch ----
__device__ float g_xnorm[BATCH * KD];
__device__ float g_keynorm[POOL * KD];
__device__ int   g_idx[BATCH * TOPK];
__device__ float g_partial[128];
__device__ int   g_sflag[128];   // sim block i done
__device__ int   g_scnt;         // sims done (==128)
__device__ int   g_gcnt;         // gathers done (==1024)

// ---- f32x2 packed-FMA helpers (sm_103a) ----
__device__ __forceinline__ void fma2(unsigned long long& acc,
                                     unsigned long long a,
                                     unsigned long long b) {
    asm("fma.rn.f32x2 %0, %1, %2, %0;" : "+l"(acc) : "l"(a), "l"(b));
}
__device__ __forceinline__ float unpack_sum(unsigned long long v) {
    float lo, hi;
    asm("mov.b64 {%0, %1}, %2;" : "=f"(lo), "=f"(hi) : "l"(v));
    return lo + hi;
}
__device__ __forceinline__ void waitge(volatile int* p, int tgt) {
    while (*p < tgt) __nanosleep(64);
}

// ============================================================
// Kernel 1: blocks 0..1023 -> per-row mean + L2 normalize
//           blocks 1024..1151 -> pool-key normalize
// (proven 80%-DRAM geometry; normalizing the SUM == normalizing
//  the mean by scale invariance)
// ============================================================
__global__ __launch_bounds__(320, 4) void k1_norm(const float4* __restrict__ x,
                                                  const float4* __restrict__ pk) {
    const int c   = threadIdx.x;                        // 0..159
    const int tid = threadIdx.y * 160 + threadIdx.x;    // 0..319
    const int lane = tid & 31, warp = tid >> 5;

    __shared__ float4 part[160];
    __shared__ float  wss[10];

    if (blockIdx.x < BATCH) {
        const int row = blockIdx.x;
        const float4* xp = x + (size_t)row * (NNODES * KD4)
                             + (size_t)threadIdx.y * 50 * KD4 + c;
        float4 a = make_float4(0.f, 0.f, 0.f, 0.f);
        #pragma unroll 10
        for (int n = 0; n < 50; n++) {
            float4 v = xp[(size_t)n * KD4];
            a.x += v.x; a.y += v.y; a.z += v.z; a.w += v.w;
        }
        if (threadIdx.y == 1) part[c] = a;
        __syncthreads();
        float ss = 0.f;
        if (threadIdx.y == 0) {
            float4 b = part[c];
            a.x += b.x; a.y += b.y; a.z += b.z; a.w += b.w;
            ss = a.x*a.x + a.y*a.y + a.z*a.z + a.w*a.w;
        }
        #pragma unroll
        for (int o = 16; o; o >>= 1) ss += __shfl_xor_sync(0xffffffffu, ss, o);
        if (lane == 0) wss[warp] = ss;
        __syncthreads();
        if (threadIdx.y == 0) {
            float tot = wss[0] + wss[1] + wss[2] + wss[3] + wss[4];
            tot = fmaxf(tot, 1e-12f);
            float rs = rsqrtf(tot);
            rs = rs * (1.5f - 0.5f * tot * rs * rs);   // NR refine
            float4* o4 = reinterpret_cast<float4*>(g_xnorm);
            o4[(size_t)row * KD4 + c] = make_float4(a.x*rs, a.y*rs, a.z*rs, a.w*rs);
        }
    } else {
        const int p = blockIdx.x - BATCH;
        float4 v = make_float4(0.f, 0.f, 0.f, 0.f);
        float ss = 0.f;
        if (tid < 160) {
            v = pk[(size_t)p * KD4 + tid];
            ss = v.x*v.x + v.y*v.y + v.z*v.z + v.w*v.w;
        }
        #pragma unroll
        for (int o = 16; o; o >>= 1) ss += __shfl_xor_sync(0xffffffffu, ss, o);
        if (lane == 0) wss[warp] = ss;
        __syncthreads();
        float tot = wss[0] + wss[1] + wss[2] + wss[3] + wss[4];
        tot = fmaxf(tot, 1e-12f);
        float rs = rsqrtf(tot);
        rs = rs * (1.5f - 0.5f * tot * rs * rs);
        if (tid < 160) {
            float4* o4 = reinterpret_cast<float4*>(g_keynorm);
            o4[(size_t)p * KD4 + tid] = make_float4(v.x*rs, v.y*rs, v.z*rs, v.w*rs);
        }
    }
}

// ============================================================
// Kernel M (merged): bids 0..127 sim GEMM (8 rows) + top-4 + flag;
// bids 128..1151 gather (spins on its sim block's flag);
// bid 1152 final reduce + usage + flag reset.
// Dependencies point to strictly lower bids -> in-order dispatch
// guarantees progress.
// ============================================================
__global__ __launch_bounds__(512, 1)
void kM(const float4* __restrict__ prompt, float* __restrict__ out) {
    const int bid = blockIdx.x;
    const int t   = threadIdx.x;
    const int w   = t >> 5, lane = t & 31;

    if (bid < M_GATHER0) {
        // ---------------- sim block: 8 rows x 128 pools ----------------
        __shared__ float xs[8][644];
        __shared__ float sims[8][132];
        __shared__ float wsum[8];

        const int i  = bid;
        const int rb = i * 8;
        const int pg = t >> 4;             // 0..31 -> pools pg*4..+3
        const int ds = t & 15;             // dim slot

        {
            const float4* xg = reinterpret_cast<const float4*>(g_xnorm);
            #pragma unroll
            for (int j = 0; j < 3; j++) {
                int l = t + 512 * j;                // covers 1280
                if (l < 1280) {
                    int r = l / 160, col = l - r * 160;
                    *reinterpret_cast<float4*>(&xs[r][col * 4]) =
                        xg[(size_t)(rb + r) * KD4 + col];
                }
            }
        }
        __syncthreads();

        const ulonglong2* kg = reinterpret_cast<const ulonglong2*>(g_keynorm);

        unsigned long long acc[4][8];      // [pool u][row r]
        #pragma unroll
        for (int u = 0; u < 4; u++)
            #pragma unroll
            for (int r = 0; r < 8; r++) acc[u][r] = 0ull;

        #pragma unroll
        for (int c = 0; c < 10; c++) {
            ulonglong2 kv[4];
            #pragma unroll
            for (int u = 0; u < 4; u++)
                kv[u] = kg[(size_t)(pg * 4 + u) * KD4 + c * 16 + ds];
            #pragma unroll
            for (int r = 0; r < 8; r++) {
                ulonglong2 xv = *reinterpret_cast<const ulonglong2*>(
                    &xs[r][c * 64 + ds * 4]);
                #pragma unroll
                for (int u = 0; u < 4; u++) {
                    fma2(acc[u][r], xv.x, kv[u].x);
                    fma2(acc[u][r], xv.y, kv[u].y);
                }
            }
        }
        #pragma unroll
        for (int u = 0; u < 4; u++) {
            #pragma unroll
            for (int r = 0; r < 8; r++) {
                float v = unpack_sum(acc[u][r]);
                #pragma unroll
                for (int o = 8; o; o >>= 1) v += __shfl_xor_sync(0xffffffffu, v, o);
                if (ds == 0) sims[r][pg * 4 + u] = v;
            }
        }
        __syncthreads();

        // similarity out (coalesced)
        for (int l = t; l < 8 * POOL; l += 512) {
            int rr = l >> 7, pp = l & 127;
            out[OUT_SIM + (size_t)(rb + rr) * POOL + pp] = sims[rr][pp];
        }

        // top-4: warps 0..7 -> rows 0..7 (monotone-bits composite key,
        // smallest index on ties -> matches jax.lax.top_k)
        if (w < 8) {
            float vals[4];
            #pragma unroll
            for (int s = 0; s < 4; s++) vals[s] = sims[w][lane + 32*s];
            float vsum = 0.f;
            #pragma unroll
            for (int k = 0; k < TOPK; k++) {
                unsigned long long best = 0ull;
                #pragma unroll
                for (int s = 0; s < 4; s++) {
                    unsigned u = __float_as_uint(vals[s]);
                    u = (u & 0x80000000u) ? ~u : (u | 0x80000000u);
                    unsigned long long comp =
                        ((unsigned long long)u << 32) | (127u - (lane + 32u*s));
                    if (comp > best) best = comp;
                }
                #pragma unroll
                for (int o = 16; o; o >>= 1) {
                    unsigned long long other = __shfl_xor_sync(0xffffffffu, best, o);
                    if (other > best) best = other;
                }
                unsigned pool = 127u - (unsigned)(best & 0xffffffffu);
                unsigned ub = (unsigned)(best >> 32);
                unsigned orig = (ub & 0x80000000u) ? (ub ^ 0x80000000u) : ~ub;
                vsum += __uint_as_float(orig);
                if (lane == (int)(pool & 31u)) vals[pool >> 5] = -1e30f;
                if (lane == 0) g_idx[(rb + w) * TOPK + k] = (int)pool;
            }
            if (lane == 0) wsum[w] = vsum;
        }
        __syncthreads();

        if (t == 0) {
            float s = 0.f;
            #pragma unroll
            for (int j = 0; j < 8; j++) s += wsum[j];  // fixed order
            g_partial[i] = s;
        }
        __syncthreads();
        __threadfence();   // publish g_idx/g_partial before flag
        if (t == 0) {
            atomicAdd(&g_sflag[i], 1);
            atomicAdd(&g_scnt, 1);
        }

    } else if (bid < M_FIN) {
        // ---------------- gather block: one batch row ----------------
        const int b = bid - M_GATHER0;
        if (t == 0) { waitge(&g_sflag[b >> 3], 1); __threadfence(); }
        __syncthreads();

        int idxs[TOPK];
        #pragma unroll
        for (int k = 0; k < TOPK; k++) idxs[k] = g_idx[b * TOPK + k];

        float4 vals[4];
        #pragma unroll
        for (int j = 0; j < 4; j++) {
            int pos = t + 512 * j;          // 0..2047
            int k   = pos / PD4;
            int off = pos - k * PD4;
            vals[j] = prompt[(size_t)idxs[k] * PD4 + off];
        }
        float4 vtail = make_float4(0.f,0.f,0.f,0.f);
        if (t < 256) vtail = prompt[(size_t)idxs[3] * PD4 + (2048 + t - 3 * PD4)];

        float4* dst = reinterpret_cast<float4*>(out) + (size_t)b * (TOPK * PD4);
        #pragma unroll
        for (int j = 0; j < 4; j++) dst[t + 512 * j] = vals[j];
        if (t < 256) dst[2048 + t] = vtail;

        __syncthreads();
        if (t == 0) atomicAdd(&g_gcnt, 1);  // past our flag read -> reset safe

    } else {
        // ---------------- final: reduce_sim + usage + reset ----------------
        __shared__ float red[128];
        __shared__ int   histo[128];
        if (t == 0) { waitge(&g_scnt, 128); __threadfence(); }
        __syncthreads();
        if (t < 128) { red[t] = g_partial[t]; histo[t] = 0; }
        __syncthreads();
        #pragma unroll
        for (int o = 64; o; o >>= 1) {
            if (t < o) red[t] += red[t + o];
            __syncthreads();
        }
        if (t == 0) out[OUT_RS] = red[0] * (1.0f / (float)BATCH);
        #pragma unroll
        for (int j = 0; j < 8; j++)
            atomicAdd(&histo[g_idx[t * 8 + j]], 1);
        __syncthreads();
        if (t < 128) out[OUT_US + t] = (float)histo[t];

        // reset for next graph replay: wait until every gather has passed
        // its flag-wait (g_gcnt==1024), then zero all flags.
        if (t == 0) waitge(&g_gcnt, 1024);
        __syncthreads();
        if (t < 128) g_sflag[t] = 0;
        if (t == 128) g_scnt = 0;
        if (t == 129) g_gcnt = 0;
    }
}

// ============================================================
extern "C" void kernel_launch(void* const* d_in, const int* in_sizes, int n_in,
                              void* d_out, int out_size) {
    const float* x      = (const float*)d_in[0];  // [1024, 100, 640]
    const float* prompt = (const float*)d_in[1];  // [128, 1, 2304]
    const float* pkey   = (const float*)d_in[2];  // [128, 640]
    float* out = (float*)d_out;

    k1_norm<<<BATCH + POOL, dim3(160, 2)>>>(
        reinterpret_cast<const float4*>(x),
        reinterpret_cast<const float4*>(pkey));
    kM<<<M_BLOCKS, 512>>>(reinterpret_cast<const float4*>(prompt), out);
}

// round 11
// speedup vs baseline: 1.1134x; 1.0819x over previous
#include <cuda_runtime.h>
#include <cstdint>

// ---- problem constants ----
#define BATCH   1024
#define NNODES  100
#define KD      640      // key dim (5*128)
#define KD4     160      // key dim in float4
#define POOL    128
#define TOPK    4
#define PD      2304     // prompt dim
#define PD4     576

// ---- output layout (flat float32, reference return order) ----
#define OUT_RS  (BATCH*TOPK*PD)          // 9437184
#define OUT_SIM (OUT_RS + 1)             // 9437185
#define OUT_US  (OUT_SIM + BATCH*POOL)   // 9568257

// ---- kernel-1 roles: bids 0..127 keys (wave 1), 128..639 x-work ----
#define B_WORK0  128
#define NB1      640

// ---- device scratch ----
__device__ float g_keyT[KD * POOL];   // TRANSPOSED normalized keys [d][p]
__device__ int   g_idx[BATCH * TOPK];
__device__ float g_partial[512];
__device__ int   g_keys;              // monotonic: no reset needed (replays
                                      // rewrite identical values; benign race)

// ---- f32x2 packed-FMA helpers (sm_103a) ----
__device__ __forceinline__ void fma2(unsigned long long& acc,
                                     unsigned long long a,
                                     unsigned long long b) {
    asm("fma.rn.f32x2 %0, %1, %2, %0;" : "+l"(acc) : "l"(a), "l"(b));
}
__device__ __forceinline__ unsigned long long pack2(float v) {
    unsigned long long r;
    asm("mov.b64 %0, {%1, %1};" : "=l"(r) : "f"(v));
    return r;
}
__device__ __forceinline__ void unpack2(unsigned long long v, float& lo, float& hi) {
    asm("mov.b64 {%0, %1}, %2;" : "=f"(lo), "=f"(hi) : "l"(v));
}
__device__ __forceinline__ void waitge(volatile int* p, int tgt) {
    while (*p < tgt) __nanosleep(64);
}

// ============================================================
// Kernel 1: bids 0..127  -> key normalize -> TRANSPOSED store
//           bids 128..639 -> 2 x-rows: stream+normalize -> smem,
//                            then in-block sim GEMM + top-4.
// Streaming geometry = proven 80%-DRAM k1 (50 nodes/thread, unroll 10).
// GEMM overlaps other blocks' streaming; keys read coalesced from L2.
// ============================================================
__global__ __launch_bounds__(640, 2)
void k1_fused(const float4* __restrict__ x, const float4* __restrict__ pk,
              float* __restrict__ out) {
    __shared__ float  xs[2][640];      // normalized rows
    __shared__ float4 part[2][160];    // half-1 partial sums
    __shared__ float  wss[20];
    __shared__ float  spart[2][10][128];
    __shared__ float  sims[2][128];
    __shared__ float  wsum[2];

    const int bid  = blockIdx.x;
    const int t    = threadIdx.x;
    const int w    = t >> 5, lane = t & 31;

    if (bid < B_WORK0) {
        // ================= key normalize -> transposed =================
        const int p = bid;
        float4 v = make_float4(0.f, 0.f, 0.f, 0.f);
        float ss = 0.f;
        if (t < 160) {
            v = pk[(size_t)p * KD4 + t];
            ss = v.x*v.x + v.y*v.y + v.z*v.z + v.w*v.w;
        }
        #pragma unroll
        for (int o = 16; o; o >>= 1) ss += __shfl_xor_sync(0xffffffffu, ss, o);
        if (lane == 0 && w < 5) wss[w] = ss;
        __syncthreads();
        if (t < 160) {
            float tot = wss[0] + wss[1] + wss[2] + wss[3] + wss[4];
            tot = fmaxf(tot, 1e-12f);
            float rs = rsqrtf(tot);
            rs = rs * (1.5f - 0.5f * tot * rs * rs);   // NR refine
            const int d = 4 * t;
            g_keyT[(size_t)(d+0) * POOL + p] = v.x * rs;
            g_keyT[(size_t)(d+1) * POOL + p] = v.y * rs;
            g_keyT[(size_t)(d+2) * POOL + p] = v.z * rs;
            g_keyT[(size_t)(d+3) * POOL + p] = v.w * rs;
        }
        __syncthreads();
        if (t == 0) { __threadfence(); atomicAdd(&g_keys, 1); }

    } else {
        // ================= x work block: 2 rows =================
        const int i  = bid - B_WORK0;
        const int rb = i * 2;

        // ---- phase A: stream mean + L2 normalize -> smem ----
        // thread = (half, row, col); 50 nodes each (proven geometry).
        // Normalizing the SUM == normalizing the mean (scale invariance).
        {
            const int half = t / 320;
            const int rem  = t - half * 320;
            const int r    = rem / 160;
            const int c    = rem - r * 160;
            const float4* xp = x + (size_t)(rb + r) * (NNODES * KD4)
                                 + (size_t)half * 50 * KD4 + c;
            float4 a = make_float4(0.f, 0.f, 0.f, 0.f);
            #pragma unroll 10
            for (int n = 0; n < 50; n++) {
                float4 v = xp[(size_t)n * KD4];
                a.x += v.x; a.y += v.y; a.z += v.z; a.w += v.w;
            }
            if (half == 1) part[r][c] = a;
            __syncthreads();
            float ss = 0.f;
            if (half == 0) {
                float4 b = part[r][c];
                a.x += b.x; a.y += b.y; a.z += b.z; a.w += b.w;
                ss = a.x*a.x + a.y*a.y + a.z*a.z + a.w*a.w;
            }
            #pragma unroll
            for (int o = 16; o; o >>= 1) ss += __shfl_xor_sync(0xffffffffu, ss, o);
            if (lane == 0 && w < 10) wss[w] = ss;   // warps 0-4 row0, 5-9 row1
            __syncthreads();
            if (half == 0) {
                const int wb = r * 5;
                float tot = wss[wb] + wss[wb+1] + wss[wb+2] + wss[wb+3] + wss[wb+4];
                tot = fmaxf(tot, 1e-12f);
                float rs = rsqrtf(tot);
                rs = rs * (1.5f - 0.5f * tot * rs * rs);
                xs[r][c*4+0] = a.x*rs; xs[r][c*4+1] = a.y*rs;
                xs[r][c*4+2] = a.z*rs; xs[r][c*4+3] = a.w*rs;
            }
        }

        // ---- phase B: wait keys (done ~40us ago; free) ----
        if (t == 0) { waitge(&g_keys, POOL); __threadfence(); }
        __syncthreads();

        // ---- phase C: sim GEMM. warp w: row = w/10, dims [64g,64g+64),
        //      g = w%10; lane owns pools 4*lane..+3 (coalesced LDG.128).
        {
            const int r = w / 10;
            const int g = w - r * 10;
            const int d0 = g * 64;
            const ulonglong2* kT =
                reinterpret_cast<const ulonglong2*>(g_keyT);

            unsigned long long a01 = 0ull, a23 = 0ull;
            #pragma unroll 4
            for (int j = 0; j < 64; j++) {
                const int d = d0 + j;
                ulonglong2 kv = kT[(size_t)d * 32 + lane];
                unsigned long long xx = pack2(xs[r][d]);
                fma2(a01, xx, kv.x);
                fma2(a23, xx, kv.y);
            }
            float p0, p1, p2, p3;
            unpack2(a01, p0, p1);
            unpack2(a23, p2, p3);
            spart[r][g][4*lane+0] = p0;
            spart[r][g][4*lane+1] = p1;
            spart[r][g][4*lane+2] = p2;
            spart[r][g][4*lane+3] = p3;
        }
        __syncthreads();

        // ---- reduce 10 partials, write sim output ----
        if (t < 256) {
            const int rr = t >> 7, pp = t & 127;
            float s = 0.f;
            #pragma unroll
            for (int g = 0; g < 10; g++) s += spart[rr][g][pp];  // fixed order
            sims[rr][pp] = s;
            out[OUT_SIM + (size_t)(rb + rr) * POOL + pp] = s;
        }
        __syncthreads();

        // ---- top-4 (warps 0..1 -> rows 0..1) ----
        // monotone-bits composite key, smallest index on ties (jax.lax.top_k)
        if (w < 2) {
            float vals[4];
            #pragma unroll
            for (int s = 0; s < 4; s++) vals[s] = sims[w][lane + 32*s];
            float vsum = 0.f;
            #pragma unroll
            for (int k = 0; k < TOPK; k++) {
                unsigned long long best = 0ull;
                #pragma unroll
                for (int s = 0; s < 4; s++) {
                    unsigned u = __float_as_uint(vals[s]);
                    u = (u & 0x80000000u) ? ~u : (u | 0x80000000u);
                    unsigned long long comp =
                        ((unsigned long long)u << 32) | (127u - (lane + 32u*s));
                    if (comp > best) best = comp;
                }
                #pragma unroll
                for (int o = 16; o; o >>= 1) {
                    unsigned long long other = __shfl_xor_sync(0xffffffffu, best, o);
                    if (other > best) best = other;
                }
                unsigned pool = 127u - (unsigned)(best & 0xffffffffu);
                unsigned ub = (unsigned)(best >> 32);
                unsigned orig = (ub & 0x80000000u) ? (ub ^ 0x80000000u) : ~ub;
                vsum += __uint_as_float(orig);
                if (lane == (int)(pool & 31u)) vals[pool >> 5] = -1e30f;
                if (lane == 0) g_idx[(rb + w) * TOPK + k] = (int)pool;
            }
            if (lane == 0) wsum[w] = vsum;
        }
        __syncthreads();
        if (t == 0) g_partial[i] = wsum[0] + wsum[1];   // fixed order
    }
}

// ============================================================
// Kernel 2: blocks 0..1023 -> gather (9 independent float4/thread,
// batch-load then batch-store). Block 1024 -> final reduce + usage.
// ============================================================
__global__ __launch_bounds__(256) void k2_gather_final(const float4* __restrict__ prompt,
                                                       float* __restrict__ out) {
    if (blockIdx.x < BATCH) {
        const int b = blockIdx.x;
        const int t = threadIdx.x;
        int idxs[TOPK];
        #pragma unroll
        for (int k = 0; k < TOPK; k++) idxs[k] = g_idx[b * TOPK + k];

        float4 vals[9];
        #pragma unroll
        for (int j = 0; j < 9; j++) {
            int pos = t + 256 * j;          // 0..2303 over [K=4][PD4=576]
            int k   = pos / PD4;
            int off = pos - k * PD4;
            vals[j] = prompt[(size_t)idxs[k] * PD4 + off];
        }
        float4* dst = reinterpret_cast<float4*>(out) + (size_t)b * (TOPK * PD4);
        #pragma unroll
        for (int j = 0; j < 9; j++) dst[t + 256 * j] = vals[j];
    } else {
        __shared__ float red[256];
        __shared__ int   histo[128];
        const int t = threadIdx.x;
        red[t] = g_partial[t] + g_partial[t + 256];   // fixed order
        if (t < 128) histo[t] = 0;
        __syncthreads();
        #pragma unroll
        for (int o = 128; o; o >>= 1) {
            if (t < o) red[t] += red[t + o];
            __syncthreads();
        }
        if (t == 0) out[OUT_RS] = red[0] * (1.0f / (float)BATCH);
        #pragma unroll
        for (int j = 0; j < 16; j++)
            atomicAdd(&histo[g_idx[t * 16 + j]], 1);
        __syncthreads();
        if (t < 128) out[OUT_US + t] = (float)histo[t];
    }
}

// ============================================================
extern "C" void kernel_launch(void* const* d_in, const int* in_sizes, int n_in,
                              void* d_out, int out_size) {
    const float* x      = (const float*)d_in[0];  // [1024, 100, 640]
    const float* prompt = (const float*)d_in[1];  // [128, 1, 2304]
    const float* pkey   = (const float*)d_in[2];  // [128, 640]
    float* out = (float*)d_out;

    k1_fused<<<NB1, 640>>>(reinterpret_cast<const float4*>(x),
                           reinterpret_cast<const float4*>(pkey), out);
    k2_gather_final<<<BATCH + 1, 256>>>(
        reinterpret_cast<const float4*>(prompt), out);
}

// round 12
// speedup vs baseline: 1.2224x; 1.0980x over previous
#include <cuda_runtime.h>
#include <cstdint>

// ---- problem constants ----
#define BATCH   1024
#define NNODES  100
#define KD      640      // key dim (5*128)
#define KD4     160      // key dim in float4
#define POOL    128
#define TOPK    4
#define PD      2304     // prompt dim
#define PD4     576

// ---- output layout (flat float32, reference return order) ----
#define OUT_RS  (BATCH*TOPK*PD)          // 9437184
#define OUT_SIM (OUT_RS + 1)             // 9437185
#define OUT_US  (OUT_SIM + BATCH*POOL)   // 9568257

// ---- device scratch ----
__device__ float g_xnorm[BATCH * KD];
__device__ float g_keynorm[POOL * KD];
__device__ int   g_idx[BATCH * TOPK];
__device__ float g_partial[128];
__device__ int   g_scnt;    // sim blocks done (==128); reset by final block

// ---- f32x2 packed-FMA helpers (sm_103a) ----
__device__ __forceinline__ void fma2(unsigned long long& acc,
                                     unsigned long long a,
                                     unsigned long long b) {
    asm("fma.rn.f32x2 %0, %1, %2, %0;" : "+l"(acc) : "l"(a), "l"(b));
}
__device__ __forceinline__ float unpack_sum(unsigned long long v) {
    float lo, hi;
    asm("mov.b64 {%0, %1}, %2;" : "=f"(lo), "=f"(hi) : "l"(v));
    return lo + hi;
}
__device__ __forceinline__ void waitge(volatile int* p, int tgt) {
    while (*p < tgt) __nanosleep(64);
}

// ============================================================
// Kernel 1: blocks 0..1023 -> per-row mean + L2 normalize
//           blocks 1024..1151 -> pool-key normalize
// (proven 80%-DRAM geometry; normalizing the SUM == normalizing
//  the mean by scale invariance)
// ============================================================
__global__ __launch_bounds__(320, 4) void k1_norm(const float4* __restrict__ x,
                                                  const float4* __restrict__ pk) {
    const int c   = threadIdx.x;                        // 0..159
    const int tid = threadIdx.y * 160 + threadIdx.x;    // 0..319
    const int lane = tid & 31, warp = tid >> 5;

    __shared__ float4 part[160];
    __shared__ float  wss[10];

    if (blockIdx.x < BATCH) {
        const int row = blockIdx.x;
        const float4* xp = x + (size_t)row * (NNODES * KD4)
                             + (size_t)threadIdx.y * 50 * KD4 + c;
        float4 a = make_float4(0.f, 0.f, 0.f, 0.f);
        #pragma unroll 10
        for (int n = 0; n < 50; n++) {
            float4 v = xp[(size_t)n * KD4];
            a.x += v.x; a.y += v.y; a.z += v.z; a.w += v.w;
        }
        if (threadIdx.y == 1) part[c] = a;
        __syncthreads();
        float ss = 0.f;
        if (threadIdx.y == 0) {
            float4 b = part[c];
            a.x += b.x; a.y += b.y; a.z += b.z; a.w += b.w;
            ss = a.x*a.x + a.y*a.y + a.z*a.z + a.w*a.w;
        }
        #pragma unroll
        for (int o = 16; o; o >>= 1) ss += __shfl_xor_sync(0xffffffffu, ss, o);
        if (lane == 0) wss[warp] = ss;
        __syncthreads();
        if (threadIdx.y == 0) {
            float tot = wss[0] + wss[1] + wss[2] + wss[3] + wss[4];
            tot = fmaxf(tot, 1e-12f);
            float rs = rsqrtf(tot);
            rs = rs * (1.5f - 0.5f * tot * rs * rs);   // NR refine
            float4* o4 = reinterpret_cast<float4*>(g_xnorm);
            o4[(size_t)row * KD4 + c] = make_float4(a.x*rs, a.y*rs, a.z*rs, a.w*rs);
        }
    } else {
        const int p = blockIdx.x - BATCH;
        float4 v = make_float4(0.f, 0.f, 0.f, 0.f);
        float ss = 0.f;
        if (tid < 160) {
            v = pk[(size_t)p * KD4 + tid];
            ss = v.x*v.x + v.y*v.y + v.z*v.z + v.w*v.w;
        }
        #pragma unroll
        for (int o = 16; o; o >>= 1) ss += __shfl_xor_sync(0xffffffffu, ss, o);
        if (lane == 0) wss[warp] = ss;
        __syncthreads();
        float tot = wss[0] + wss[1] + wss[2] + wss[3] + wss[4];
        tot = fmaxf(tot, 1e-12f);
        float rs = rsqrtf(tot);
        rs = rs * (1.5f - 0.5f * tot * rs * rs);
        if (tid < 160) {
            float4* o4 = reinterpret_cast<float4*>(g_keynorm);
            o4[(size_t)p * KD4 + tid] = make_float4(v.x*rs, v.y*rs, v.z*rs, v.w*rs);
        }
    }
}

// ============================================================
// Kernel M2: blocks 0..127 -> sim GEMM (8 rows x 128 pools, proven
// R5 tile) + top-4 + sim write + IN-BLOCK gather of the 32 selected
// prompts. Block 128 -> final reduce + usage (+ counter reset).
// Single wave at 1 CTA/SM; gather happens with no extra launch.
// ============================================================
__global__ __launch_bounds__(512)
void kM2(const float4* __restrict__ prompt, float* __restrict__ out) {
    const int bid = blockIdx.x;
    const int t   = threadIdx.x;
    const int w   = t >> 5, lane = t & 31;

    if (bid < POOL) {
        __shared__ float xs[8][644];
        __shared__ float sims[8][132];
        __shared__ float wsum[8];
        __shared__ int   sidx[32];

        const int rb = bid * 8;
        const int pg = t >> 4;             // 0..31 -> pools pg*4..+3
        const int ds = t & 15;             // dim slot

        // stage 8 x rows (coalesced)
        {
            const float4* xg = reinterpret_cast<const float4*>(g_xnorm);
            #pragma unroll
            for (int i = 0; i < 3; i++) {
                int l = t + 512 * i;                // covers 1280
                if (l < 1280) {
                    int r = l / 160, col = l - r * 160;
                    *reinterpret_cast<float4*>(&xs[r][col * 4]) =
                        xg[(size_t)(rb + r) * KD4 + col];
                }
            }
        }
        __syncthreads();

        const ulonglong2* kg = reinterpret_cast<const ulonglong2*>(g_keynorm);

        unsigned long long acc[4][8];      // [pool u][row r]
        #pragma unroll
        for (int u = 0; u < 4; u++)
            #pragma unroll
            for (int r = 0; r < 8; r++) acc[u][r] = 0ull;

        #pragma unroll
        for (int c = 0; c < 10; c++) {
            ulonglong2 kv[4];
            #pragma unroll
            for (int u = 0; u < 4; u++)
                kv[u] = kg[(size_t)(pg * 4 + u) * KD4 + c * 16 + ds];
            #pragma unroll
            for (int r = 0; r < 8; r++) {
                ulonglong2 xv = *reinterpret_cast<const ulonglong2*>(
                    &xs[r][c * 64 + ds * 4]);
                #pragma unroll
                for (int u = 0; u < 4; u++) {
                    fma2(acc[u][r], xv.x, kv[u].x);
                    fma2(acc[u][r], xv.y, kv[u].y);
                }
            }
        }

        #pragma unroll
        for (int u = 0; u < 4; u++) {
            #pragma unroll
            for (int r = 0; r < 8; r++) {
                float v = unpack_sum(acc[u][r]);
                #pragma unroll
                for (int o = 8; o; o >>= 1) v += __shfl_xor_sync(0xffffffffu, v, o);
                if (ds == 0) sims[r][pg * 4 + u] = v;
            }
        }
        __syncthreads();

        // similarity output (coalesced)
        for (int l = t; l < 8 * POOL; l += 512) {
            int rr = l >> 7, pp = l & 127;
            out[OUT_SIM + (size_t)(rb + rr) * POOL + pp] = sims[rr][pp];
        }

        // top-4: warps 0..7 -> rows 0..7 (monotone-bits composite key,
        // smallest index on ties -> matches jax.lax.top_k)
        if (w < 8) {
            float vals[4];
            #pragma unroll
            for (int s = 0; s < 4; s++) vals[s] = sims[w][lane + 32*s];
            float vsum = 0.f;
            #pragma unroll
            for (int k = 0; k < TOPK; k++) {
                unsigned long long best = 0ull;
                #pragma unroll
                for (int s = 0; s < 4; s++) {
                    unsigned u = __float_as_uint(vals[s]);
                    u = (u & 0x80000000u) ? ~u : (u | 0x80000000u);
                    unsigned long long comp =
                        ((unsigned long long)u << 32) | (127u - (lane + 32u*s));
                    if (comp > best) best = comp;
                }
                #pragma unroll
                for (int o = 16; o; o >>= 1) {
                    unsigned long long other = __shfl_xor_sync(0xffffffffu, best, o);
                    if (other > best) best = other;
                }
                unsigned pool = 127u - (unsigned)(best & 0xffffffffu);
                unsigned ub = (unsigned)(best >> 32);
                unsigned orig = (ub & 0x80000000u) ? (ub ^ 0x80000000u) : ~ub;
                vsum += __uint_as_float(orig);
                if (lane == (int)(pool & 31u)) vals[pool >> 5] = -1e30f;
                if (lane == 0) {
                    g_idx[(rb + w) * TOPK + k] = (int)pool;
                    sidx[w * 4 + k] = (int)pool;
                }
            }
            if (lane == 0) wsum[w] = vsum;
        }
        __syncthreads();

        if (t == 0) {
            float s = 0.f;
            #pragma unroll
            for (int j = 0; j < 8; j++) s += wsum[j];   // fixed order
            g_partial[bid] = s;
        }
        __syncthreads();
        __threadfence();   // publish g_idx/g_partial before counter
        if (t == 0) atomicAdd(&g_scnt, 1);

        // in-block gather: 32 segments x 576 float4 = 18432, 36/thread,
        // batched 6-deep for MLP.
        float4* outbp = reinterpret_cast<float4*>(out);
        #pragma unroll
        for (int s0 = 0; s0 < 36; s0 += 6) {
            float4 v[6]; int di[6];
            #pragma unroll
            for (int k = 0; k < 6; k++) {
                int i   = t + 512 * (s0 + k);
                int seg = i / PD4;
                int off = i - seg * PD4;
                v[k]  = prompt[(size_t)sidx[seg] * PD4 + off];
                di[k] = (rb * 4 + seg) * PD4 + off;
            }
            #pragma unroll
            for (int k = 0; k < 6; k++) outbp[di[k]] = v[k];
        }

    } else {
        // ---------------- final: reduce_sim + usage + reset ----------------
        __shared__ float red[128];
        __shared__ int   histo[128];
        if (t == 0) { waitge(&g_scnt, 128); __threadfence(); }
        __syncthreads();
        if (t < 128) { red[t] = g_partial[t]; histo[t] = 0; }
        __syncthreads();
        #pragma unroll
        for (int o = 64; o; o >>= 1) {
            if (t < o) red[t] += red[t + o];
            __syncthreads();
        }
        if (t == 0) out[OUT_RS] = red[0] * (1.0f / (float)BATCH);
        #pragma unroll
        for (int j = 0; j < 8; j++)
            atomicAdd(&histo[g_idx[t * 8 + j]], 1);
        __syncthreads();
        if (t < 128) out[OUT_US + t] = (float)histo[t];
        if (t == 0) g_scnt = 0;   // reset for next graph replay
    }
}

// ============================================================
extern "C" void kernel_launch(void* const* d_in, const int* in_sizes, int n_in,
                              void* d_out, int out_size) {
    const float* x      = (const float*)d_in[0];  // [1024, 100, 640]
    const float* prompt = (const float*)d_in[1];  // [128, 1, 2304]
    const float* pkey   = (const float*)d_in[2];  // [128, 640]
    float* out = (float*)d_out;

    k1_norm<<<BATCH + POOL, dim3(160, 2)>>>(
        reinterpret_cast<const float4*>(x),
        reinterpret_cast<const float4*>(pkey));
    kM2<<<POOL + 1, 512>>>(reinterpret_cast<const float4*>(prompt), out);
}